// round 17
// baseline (speedup 1.0000x reference)
#include <cuda_runtime.h>
#include <cuda_fp16.h>
#include <cstdint>

#define BSZ 4096
#define RR 36
#define TT 32
#define LL 1024
#define LK 256

// ---------------- scratch (__device__ globals; no allocations allowed) ----------------
__device__ __half g_sHi[BSZ * LL];   // fp16(s)
__device__ __half g_s2[BSZ * LL];    // fp16(s*s)
__device__ __half g_gg[BSZ * LL];    // fp16(gate * c_hat)
__device__ __half g_hh[BSZ * LL];    // fp16(gate*gate)
__device__ __half g_rHi[BSZ * LK];   // fp16(cap_repr)
__device__ __half g_rLo[BSZ * LK];   // fp16(residual)
__device__ __half g_wH[LL * LK];     // fp16(W_kp)
__device__ float g_invn[BSZ];
__device__ float g_rsd[(size_t)BSZ * BSZ];   // rsqrt(denom) scratch (64 MB)

// ---------------- helpers ----------------
__device__ __forceinline__ uint32_t smem_u32(const void* p) {
    uint32_t a;
    asm("{ .reg .u64 t; cvta.to.shared.u64 t, %1; cvt.u32.u64 %0, t; }" : "=r"(a) : "l"(p));
    return a;
}
__device__ __forceinline__ void cp16b(uint32_t sa, const void* g) {
    asm volatile("cp.async.cg.shared.global [%0], [%1], 16;" ::"r"(sa), "l"(g));
}
__device__ __forceinline__ void ldsm4(uint32_t r[4], uint32_t sa) {
    asm volatile("ldmatrix.sync.aligned.m8n8.x4.shared.b16 {%0,%1,%2,%3}, [%4];"
                 : "=r"(r[0]), "=r"(r[1]), "=r"(r[2]), "=r"(r[3]) : "r"(sa));
}
__device__ __forceinline__ void mma_f16(float d[4], const uint32_t a[4],
                                        uint32_t b0, uint32_t b1) {
    asm("mma.sync.aligned.m16n8k16.row.col.f32.f16.f16.f32 "
        "{%0,%1,%2,%3}, {%4,%5,%6,%7}, {%8,%9}, {%0,%1,%2,%3};"
        : "+f"(d[0]), "+f"(d[1]), "+f"(d[2]), "+f"(d[3])
        : "r"(a[0]), "r"(a[1]), "r"(a[2]), "r"(a[3]), "r"(b0), "r"(b1));
}

// ---------------- K1: s = img.sum(axis=1), emit fp16 s and s^2 ----------------
__global__ void k_sum(const float* __restrict__ img) {
    const int b = blockIdx.x, t = threadIdx.x;
    const float4* p = reinterpret_cast<const float4*>(img + (size_t)b * RR * LL) + t;
    float4 acc = make_float4(0.f, 0.f, 0.f, 0.f);
#pragma unroll
    for (int r = 0; r < RR; ++r) {
        float4 v = p[r * (LL / 4)];
        acc.x += v.x; acc.y += v.y; acc.z += v.z; acc.w += v.w;
    }
    const size_t o = (size_t)b * LL + t * 4;
    float s[4] = {acc.x, acc.y, acc.z, acc.w};
#pragma unroll
    for (int c = 0; c < 4; ++c) {
        g_sHi[o + c] = __float2half(s[c]);
        g_s2[o + c]  = __float2half(s[c] * s[c]);
    }
}

// ---------------- K2: inv_norm of cap0 rows ----------------
__global__ void k_norm(const float* __restrict__ cap) {
    const int b = blockIdx.x, t = threadIdx.x;
    const float4 v = reinterpret_cast<const float4*>(cap + (size_t)b * TT * LL)[t];
    float ss = v.x * v.x + v.y * v.y + v.z * v.z + v.w * v.w;
#pragma unroll
    for (int o = 16; o; o >>= 1) ss += __shfl_xor_sync(0xffffffffu, ss, o);
    __shared__ float red[8];
    if ((t & 31) == 0) red[t >> 5] = ss;
    __syncthreads();
    if (t == 0) {
        float tot = 0.f;
#pragma unroll
        for (int w = 0; w < 8; ++w) tot += red[w];
        g_invn[b] = rsqrtf(tot);
    }
}

// ---------------- K3: cap_repr = cap0 @ W_red^T + b_red (emit fp16 splits) ----------------
__global__ __launch_bounds__(256) void k_repr(const float* __restrict__ cap,
                                              const float* __restrict__ Wred,
                                              const float* __restrict__ bred) {
    __shared__ float sc[8][LL];
    const int b0 = blockIdx.x * 8, t = threadIdx.x;
#pragma unroll
    for (int bb = 0; bb < 8; ++bb)
        reinterpret_cast<float4*>(sc[bb])[t] =
            reinterpret_cast<const float4*>(cap + (size_t)(b0 + bb) * TT * LL)[t];
    __syncthreads();

    float acc[8] = {0.f, 0.f, 0.f, 0.f, 0.f, 0.f, 0.f, 0.f};
    const float4* w = reinterpret_cast<const float4*>(Wred + (size_t)t * LL);
    for (int k4 = 0; k4 < LL / 4; ++k4) {
        const float4 wv = w[k4];
#pragma unroll
        for (int bb = 0; bb < 8; ++bb) {
            const float4 cv = reinterpret_cast<const float4*>(sc[bb])[k4];
            acc[bb] += wv.x * cv.x + wv.y * cv.y + wv.z * cv.z + wv.w * cv.w;
        }
    }
    const float bias = bred[t];
#pragma unroll
    for (int bb = 0; bb < 8; ++bb) {
        const float v = acc[bb] + bias;
        const __half hi = __float2half(v);
        const __half lo = __float2half(v - __half2float(hi));
        g_rHi[(size_t)(b0 + bb) * LK + t] = hi;
        g_rLo[(size_t)(b0 + bb) * LK + t] = lo;
    }
}

// ---------------- K3b: Wkp -> fp16 ----------------
__global__ void k_wsplit(const float* __restrict__ Wkp) {
    const int i = blockIdx.x * 256 + threadIdx.x;     // float4 index
    const float4 v = reinterpret_cast<const float4*>(Wkp)[i];
    __half2 h0 = __floats2half2_rn(v.x, v.y);
    __half2 h1 = __floats2half2_rn(v.z, v.w);
    uint2 pk;
    pk.x = *reinterpret_cast<uint32_t*>(&h0);
    pk.y = *reinterpret_cast<uint32_t*>(&h1);
    *reinterpret_cast<uint2*>(g_wH + (size_t)i * 4) = pk;
}

// ---------------- K4: gate via split-fp16 HMMA; fused sigmoid epilogue ----------------
// z[b,l] = (rHi+rLo)[b,:] . wH[l,:],  K=256
#define GKC 64
#define GSTR 72                       // fp16 elems per smem row (144B) — conflict-free LDSM
#define GTILE (128 * GSTR)            // elems
#define GTILE_B (GTILE * 2)           // bytes
#define GNARR 3                       // rHi, rLo | wH
#define GSTAGE_B (GNARR * GTILE_B)    // 55296 B
#define GNKT (LK / GKC)               // 4
#define SMEM_GATE (2 * GSTAGE_B)      // 110592 B

__device__ __forceinline__ void load_stage_g(uint32_t sstage, int i0, int j0, int k0, int t) {
    const int c = t & 7;              // 16B chunk within 128B of k
    const int r0 = t >> 3;            // 0..31
    const __half* srcs[GNARR] = {g_rHi, g_rLo, g_wH};
#pragma unroll
    for (int a = 0; a < GNARR; ++a) {
        const int base = (a < 2) ? i0 : j0;
        const __half* g = srcs[a] + (size_t)(base + r0) * LK + k0 + c * 8;
        const uint32_t sa = sstage + a * GTILE_B + r0 * (GSTR * 2) + c * 16;
#pragma unroll
        for (int e = 0; e < 4; ++e)
            cp16b(sa + e * 32 * (GSTR * 2), g + (size_t)e * 32 * LK);
    }
}

__global__ __launch_bounds__(256, 1) void k_gate(const float* __restrict__ cap,
                                                 const float* __restrict__ bkp) {
    extern __shared__ __half smg[];
    const uint32_t sbase = smem_u32(smg);
    const int t = threadIdx.x;
    const int lane = t & 31, wid = t >> 5;
    const int wm = wid >> 2, wn = wid & 3;     // 2x4 warp grid, warp tile 64x32
    const int lr = lane >> 2, lc = lane & 3;
    const int i0 = blockIdx.y * 128;           // batch
    const int j0 = blockIdx.x * 128;           // l feature

    float z[4][4][4];
#pragma unroll
    for (int a = 0; a < 4; ++a)
#pragma unroll
        for (int b = 0; b < 4; ++b)
#pragma unroll
            for (int c = 0; c < 4; ++c) z[a][b][c] = 0.f;

    const int a_row_l = lane & 15;
    const int a_col_l = (lane >> 4) * 8;
    const int b_row_l = (lane & 7) + ((lane >> 4) << 3);
    const int b_col_l = ((lane >> 3) & 1) * 8;

    load_stage_g(sbase, i0, j0, 0, t);
    asm volatile("cp.async.commit_group;");

#pragma unroll 1
    for (int kt = 0; kt < GNKT; ++kt) {
        const int st = kt & 1;
        if (kt + 1 < GNKT) {
            load_stage_g(sbase + (st ^ 1) * GSTAGE_B, i0, j0, (kt + 1) * GKC, t);
            asm volatile("cp.async.commit_group;");
            asm volatile("cp.async.wait_group 1;");
        } else {
            asm volatile("cp.async.wait_group 0;");
        }
        __syncthreads();
        const uint32_t sb = sbase + st * GSTAGE_B;
#pragma unroll
        for (int kh = 0; kh < 4; ++kh) {
            const int kofs = kh * 16;
            uint32_t BW[2][4];
#pragma unroll
            for (int n2 = 0; n2 < 2; ++n2) {
                const int brow = wn * 32 + n2 * 16 + b_row_l;
                ldsm4(BW[n2], sb + 2 * GTILE_B + (uint32_t)(brow * GSTR + kofs + b_col_l) * 2);
            }
            uint32_t A[2][2][4];   // [buf][hi/lo][frag]
            {
                const int arow = wm * 64 + a_row_l;
                const uint32_t ao = (uint32_t)(arow * GSTR + kofs + a_col_l) * 2;
                ldsm4(A[0][0], sb + 0 * GTILE_B + ao);
                ldsm4(A[0][1], sb + 1 * GTILE_B + ao);
            }
#pragma unroll
            for (int mt = 0; mt < 4; ++mt) {
                if (mt < 3) {
                    const int arow = wm * 64 + (mt + 1) * 16 + a_row_l;
                    const uint32_t ao = (uint32_t)(arow * GSTR + kofs + a_col_l) * 2;
                    ldsm4(A[(mt + 1) & 1][0], sb + 0 * GTILE_B + ao);
                    ldsm4(A[(mt + 1) & 1][1], sb + 1 * GTILE_B + ao);
                }
#pragma unroll
                for (int nt = 0; nt < 4; ++nt)
                    mma_f16(z[mt][nt], A[mt & 1][0], BW[nt >> 1][2 * (nt & 1)], BW[nt >> 1][2 * (nt & 1) + 1]);
#pragma unroll
                for (int nt = 0; nt < 4; ++nt)
                    mma_f16(z[mt][nt], A[mt & 1][1], BW[nt >> 1][2 * (nt & 1)], BW[nt >> 1][2 * (nt & 1) + 1]);
            }
        }
        __syncthreads();
    }

    // epilogue: sigmoid + combine with c_hat; emit gg, hh (fp16)
#pragma unroll
    for (int mt = 0; mt < 4; ++mt)
#pragma unroll
        for (int nt = 0; nt < 4; ++nt) {
            const int j = j0 + wn * 32 + nt * 8 + lc * 2;
            const float2 bb = *reinterpret_cast<const float2*>(bkp + j);
#pragma unroll
            for (int h = 0; h < 2; ++h) {
                const int i = i0 + wm * 64 + mt * 16 + lr + h * 8;
                const float inv = g_invn[i];
                const float2 cv = *reinterpret_cast<const float2*>(cap + (size_t)i * TT * LL + j);
                const float z0 = z[mt][nt][2 * h + 0] + bb.x;
                const float z1 = z[mt][nt][2 * h + 1] + bb.y;
                const float gt0 = 1.0f / (1.0f + expf(-z0));
                const float gt1 = 1.0f / (1.0f + expf(-z1));
                __half2 gg = __floats2half2_rn(gt0 * cv.x * inv, gt1 * cv.y * inv);
                __half2 hh = __floats2half2_rn(gt0 * gt0, gt1 * gt1);
                *reinterpret_cast<__half2*>(g_gg + (size_t)i * LL + j) = gg;
                *reinterpret_cast<__half2*>(g_hh + (size_t)i * LL + j) = hh;
            }
        }
}

// ---------------- K5a/K5b: single-GEMM kernels, occ 2 (4 warps/SMSP) ----------------
#define KC 64
#define ASTRIDE 72                    // fp16 elems per smem row (144B) — conflict-free LDSM
#define TILEE (128 * ASTRIDE)         // 9216 elems per array tile
#define TILE_B (TILEE * 2)            // 18432 bytes
#define PNARR 2                       // one A array + one B array
#define PSTAGE_B (PNARR * TILE_B)     // 36864 B per stage
#define NSTAGE 3
#define NKT (LL / KC)                 // 16
#define SMEM_PAIR (NSTAGE * PSTAGE_B) // 110592 B

__device__ __forceinline__ void load_stage_p(uint32_t sstage, const __half* Aarr,
                                             const __half* Barr, int i0, int j0,
                                             int k0, int t) {
    const int c = t & 7;              // 16B chunk within 128B of k
    const int r0 = t >> 3;            // 0..31
    const __half* gA = Aarr + (size_t)(i0 + r0) * LL + k0 + c * 8;
    const __half* gB = Barr + (size_t)(j0 + r0) * LL + k0 + c * 8;
    const uint32_t sa = sstage + r0 * (ASTRIDE * 2) + c * 16;
#pragma unroll
    for (int e = 0; e < 4; ++e) {
        cp16b(sa + e * 32 * (ASTRIDE * 2), gA + (size_t)e * 32 * LL);
        cp16b(sa + TILE_B + e * 32 * (ASTRIDE * 2), gB + (size_t)e * 32 * LL);
    }
}

// WRITE_RS: dst <- rsqrt(acc)   (denom pass)
// else:     dst <- acc * g_rsd  (numer pass, final output)
template <bool WRITE_RS>
__global__ __launch_bounds__(256, 2) void k_pair(const __half* __restrict__ Aarr,
                                                 const __half* __restrict__ Barr,
                                                 float* __restrict__ dst) {
    extern __shared__ __half sm[];
    const uint32_t sbase = smem_u32(sm);
    const int t = threadIdx.x;
    const int lane = t & 31, wid = t >> 5;
    const int wm = wid >> 2, wn = wid & 3;     // 2x4 warp grid, warp tile 64x32
    const int lr = lane >> 2, lc = lane & 3;
    const int i0 = blockIdx.y * 128, j0 = blockIdx.x * 128;

    float acc[4][4][4];
#pragma unroll
    for (int a = 0; a < 4; ++a)
#pragma unroll
        for (int b = 0; b < 4; ++b)
#pragma unroll
            for (int c = 0; c < 4; ++c) acc[a][b][c] = 0.f;

    const int a_row_l = lane & 15;
    const int a_col_l = (lane >> 4) * 8;
    const int b_row_l = (lane & 7) + ((lane >> 4) << 3);
    const int b_col_l = ((lane >> 3) & 1) * 8;

    // prologue: stages for kt=0,1 into buffers 0,1
    load_stage_p(sbase + 0 * PSTAGE_B, Aarr, Barr, i0, j0, 0 * KC, t);
    asm volatile("cp.async.commit_group;");
    load_stage_p(sbase + 1 * PSTAGE_B, Aarr, Barr, i0, j0, 1 * KC, t);
    asm volatile("cp.async.commit_group;");

    int stC = 0;
#pragma unroll 1
    for (int kt = 0; kt < NKT; ++kt) {
        if (kt + 1 < NKT) asm volatile("cp.async.wait_group 1;");
        else              asm volatile("cp.async.wait_group 0;");
        __syncthreads();
        if (kt + 2 < NKT) {
            int stW = stC + 2; if (stW >= NSTAGE) stW -= NSTAGE;
            load_stage_p(sbase + stW * PSTAGE_B, Aarr, Barr, i0, j0, (kt + 2) * KC, t);
            asm volatile("cp.async.commit_group;");
        }

        const uint32_t sb = sbase + stC * PSTAGE_B;
#pragma unroll
        for (int kh = 0; kh < 4; ++kh) {
            const int kofs = kh * 16;
            uint32_t BG[2][4];
#pragma unroll
            for (int n2 = 0; n2 < 2; ++n2) {
                const int brow = wn * 32 + n2 * 16 + b_row_l;
                ldsm4(BG[n2], sb + TILE_B + (uint32_t)(brow * ASTRIDE + kofs + b_col_l) * 2);
            }
            uint32_t A[2][4];   // double-buffered A fragments
            {
                const int arow = wm * 64 + a_row_l;
                ldsm4(A[0], sb + (uint32_t)(arow * ASTRIDE + kofs + a_col_l) * 2);
            }
#pragma unroll
            for (int mt = 0; mt < 4; ++mt) {
                if (mt < 3) {   // prefetch next mt's fragment under current MMAs
                    const int arow = wm * 64 + (mt + 1) * 16 + a_row_l;
                    ldsm4(A[(mt + 1) & 1], sb + (uint32_t)(arow * ASTRIDE + kofs + a_col_l) * 2);
                }
                const int bf = mt & 1;
#pragma unroll
                for (int nt = 0; nt < 4; ++nt)
                    mma_f16(acc[mt][nt], A[bf], BG[nt >> 1][2 * (nt & 1)], BG[nt >> 1][2 * (nt & 1) + 1]);
            }
        }
        stC = (stC + 1 == NSTAGE) ? 0 : stC + 1;
    }

    // epilogue
#pragma unroll
    for (int mt = 0; mt < 4; ++mt)
#pragma unroll
        for (int nt = 0; nt < 4; ++nt) {
            const int i = i0 + wm * 64 + mt * 16 + lr;
            const int j = j0 + wn * 32 + nt * 8 + lc * 2;
            if (WRITE_RS) {
                float2 v0, v1;
                v0.x = rsqrtf(acc[mt][nt][0]);
                v0.y = rsqrtf(acc[mt][nt][1]);
                v1.x = rsqrtf(acc[mt][nt][2]);
                v1.y = rsqrtf(acc[mt][nt][3]);
                *reinterpret_cast<float2*>(dst + (size_t)i * BSZ + j) = v0;
                *reinterpret_cast<float2*>(dst + (size_t)(i + 8) * BSZ + j) = v1;
            } else {
                const float2 r0 = *reinterpret_cast<const float2*>(g_rsd + (size_t)i * BSZ + j);
                const float2 r1 = *reinterpret_cast<const float2*>(g_rsd + (size_t)(i + 8) * BSZ + j);
                float2 v0, v1;
                v0.x = acc[mt][nt][0] * r0.x;
                v0.y = acc[mt][nt][1] * r0.y;
                v1.x = acc[mt][nt][2] * r1.x;
                v1.y = acc[mt][nt][3] * r1.y;
                *reinterpret_cast<float2*>(dst + (size_t)i * BSZ + j) = v0;
                *reinterpret_cast<float2*>(dst + (size_t)(i + 8) * BSZ + j) = v1;
            }
        }
}

// ---------------- launch ----------------
extern "C" void kernel_launch(void* const* d_in, const int* in_sizes, int n_in,
                              void* d_out, int out_size) {
    (void)in_sizes; (void)n_in; (void)out_size;
    const float* img  = (const float*)d_in[0];
    const float* cap  = (const float*)d_in[1];
    // d_in[2] = lens : unused by the reference computation
    const float* Wred = (const float*)d_in[3];
    const float* bred = (const float*)d_in[4];
    const float* Wkp  = (const float*)d_in[5];
    const float* bkp  = (const float*)d_in[6];
    float* out = (float*)d_out;

    k_sum<<<BSZ, 256>>>(img);
    k_norm<<<BSZ, 256>>>(cap);
    k_repr<<<BSZ / 8, 256>>>(cap, Wred, bred);
    k_wsplit<<<(LL * LK / 4) / 256, 256>>>(Wkp);

    cudaFuncSetAttribute(k_gate, cudaFuncAttributeMaxDynamicSharedMemorySize, SMEM_GATE);
    k_gate<<<dim3(LL / 128, BSZ / 128), 256, SMEM_GATE>>>(cap, bkp);

    float* d_rsd = nullptr;
    cudaGetSymbolAddress((void**)&d_rsd, g_rsd);

    cudaFuncSetAttribute(k_pair<true>,  cudaFuncAttributeMaxDynamicSharedMemorySize, SMEM_PAIR);
    cudaFuncSetAttribute(k_pair<false>, cudaFuncAttributeMaxDynamicSharedMemorySize, SMEM_PAIR);

    __half* p_s2 = nullptr;  cudaGetSymbolAddress((void**)&p_s2, g_s2);
    __half* p_hh = nullptr;  cudaGetSymbolAddress((void**)&p_hh, g_hh);
    __half* p_sH = nullptr;  cudaGetSymbolAddress((void**)&p_sH, g_sHi);
    __half* p_gg = nullptr;  cudaGetSymbolAddress((void**)&p_gg, g_gg);

    k_pair<true><<<dim3(BSZ / 128, BSZ / 128), 256, SMEM_PAIR>>>(p_s2, p_hh, d_rsd);
    k_pair<false><<<dim3(BSZ / 128, BSZ / 128), 256, SMEM_PAIR>>>(p_sH, p_gg, out);
}